// round 15
// baseline (speedup 1.0000x reference)
#include <cuda_runtime.h>
#include <cuda_fp16.h>
#include <cstdint>

#define Bb 64
#define Nn 50
#define Tt 30
#define Ee 300
#define EeP 320
#define FNf 400
#define Aa 200
#define Gg 400
#define KCv 960            // conv GEMM K = 3*320
#define KP 416             // padded K for attn/GX
#define MROWS (Bb*Nn*Tt)   // 96000
#define LDKH 40            // smem k-stride in halves (32 + 8 pad)
#define GBLK 25            // GRU blocks

// ---------------- scratch ----------------
__device__ __half g_X[(long)Bb * Nn * 32 * EeP];   // gathered embeddings
__device__ __half g_Wt[416 * KCv];                 // conv weights [416][960], rows>=400 zero
__device__ __half g_vT[208 * KP];                  // v^T padded [208][416]
__device__ __half g_Wih[1200 * KP];                // W_ih padded [1200][416]
__device__ __half g_Whh[1200 * Gg];                // W_hh fp16 [1200][400]
__device__ __half g_C[(long)MROWS * KP];           // conv out; pad cols 0
__device__ float  g_scores[MROWS];
__device__ float  g_alpha[MROWS];
__device__ __half g_E[3328 * KP];                  // news embed (rows>=3200 stay 0)
__device__ float  g_GX[3328L * 1200];              // GX row-major [r][1200]
__device__ float  g_GXt[Nn * 1200 * Bb];           // transposed: [n][3G][b]
__device__ __align__(16) __half g_hH[2][Bb * 408]; // fp16 h exchange, ping-pong
__device__ int    g_bar[64];

// ---------------- helpers ----------------
__device__ __forceinline__ uint32_t smem_u32(const void* p) {
    uint32_t a;
    asm("{ .reg .u64 t; cvta.to.shared.u64 t, %1; cvt.u32.u64 %0, t; }" : "=r"(a) : "l"(p));
    return a;
}
__device__ __forceinline__ float htanh(float x) {
    float r; asm("tanh.approx.f32 %0, %1;" : "=f"(r) : "f"(x)); return r;
}
__device__ __forceinline__ void cpasync16(uint32_t dst, const void* src) {
    asm volatile("cp.async.cg.shared.global [%0], [%1], 16;" :: "r"(dst), "l"(src));
}
__device__ __forceinline__ void cpcommit() { asm volatile("cp.async.commit_group;" ::: "memory"); }
template <int N> __device__ __forceinline__ void cpwait() {
    asm volatile("cp.async.wait_group %0;" :: "n"(N) : "memory");
}
__device__ __forceinline__ void mma16816(float* c, const uint32_t* a, uint32_t b0, uint32_t b1) {
    asm volatile("mma.sync.aligned.m16n8k16.row.col.f32.f16.f16.f32 "
                 "{%0,%1,%2,%3}, {%4,%5,%6,%7}, {%8,%9}, {%0,%1,%2,%3};"
                 : "+f"(c[0]), "+f"(c[1]), "+f"(c[2]), "+f"(c[3])
                 : "r"(a[0]), "r"(a[1]), "r"(a[2]), "r"(a[3]), "r"(b0), "r"(b1));
}
__device__ __forceinline__ void ldsm_x4(uint32_t& r0, uint32_t& r1, uint32_t& r2, uint32_t& r3,
                                        uint32_t addr) {
    asm volatile("ldmatrix.sync.aligned.m8n8.x4.shared.b16 {%0,%1,%2,%3}, [%4];"
                 : "=r"(r0), "=r"(r1), "=r"(r2), "=r"(r3) : "r"(addr));
}
__device__ __forceinline__ void ldsm_x2(uint32_t& r0, uint32_t& r1, uint32_t addr) {
    asm volatile("ldmatrix.sync.aligned.m8n8.x2.shared.b16 {%0,%1}, [%2];"
                 : "=r"(r0), "=r"(r1) : "r"(addr));
}

// ---------------- prep ----------------
__global__ __launch_bounds__(256) void gather_kernel(const int* __restrict__ title,
                                                     const float* __restrict__ word_emb) {
    int bn = blockIdx.x;
    __half* X = g_X + (long)bn * 32 * EeP;
    const __half z = __float2half(0.f);
    for (int i = threadIdx.x; i < EeP; i += 256) { X[i] = z; X[31 * EeP + i] = z; }
    const int* tw = title + bn * Tt;
    for (int idx = threadIdx.x; idx < Tt * EeP; idx += 256) {
        int s = idx / EeP, e = idx - s * EeP;
        float v = (e < Ee) ? word_emb[(long)tw[s] * Ee + e] : 0.f;
        X[(s + 1) * EeP + e] = __float2half_rn(v);
    }
}
__global__ void wtr_kernel(const float* __restrict__ conv_w) {
    int i = blockIdx.x * 256 + threadIdx.x;
    if (i >= 416 * KCv) return;
    int n = i / KCv, k = i - n * KCv;
    int tap = k / EeP, e = k - tap * EeP;
    float v = (n < FNf && e < Ee) ? conv_w[(tap * Ee + e) * FNf + n] : 0.f;
    g_Wt[i] = __float2half_rn(v);
}
__global__ void vtr_kernel(const float* __restrict__ v) {
    int i = blockIdx.x * 256 + threadIdx.x;
    if (i >= 208 * KP) return;
    int a = i / KP, f = i - a * KP;
    float x = (a < Aa && f < FNf) ? v[f * Aa + a] : 0.f;
    g_vT[i] = __float2half_rn(x);
}
__global__ void wihh_kernel(const float* __restrict__ W_ih) {
    int i = blockIdx.x * 256 + threadIdx.x;
    if (i >= 1200 * KP) return;
    int n = i / KP, k = i - n * KP;
    float x = (k < FNf) ? W_ih[n * FNf + k] : 0.f;
    g_Wih[i] = __float2half_rn(x);
}
__global__ void whh_kernel(const float* __restrict__ W_hh) {
    int i = blockIdx.x * 256 + threadIdx.x;
    if (i >= 1200 * Gg) return;
    g_Whh[i] = __float2half_rn(W_hh[i]);
}

// ---------------- fp16 cp.async GEMM (3-stage) with ldmatrix fragments ----------------
// EPI 0: conv rows via g_X map; bias+ReLU -> half OutH[.][416]
// EPI 1: attn; tanh.approx(+vb)*q block-reduce -> OutF[row] (g_scores)
// EPI 2: GX; bias; plain fp32 store to OutF[r][1200]
template <int MT, int NT, int EPI, int MINB>
__global__ __launch_bounds__(256, MINB) void hgemm(const __half* __restrict__ A,
                                                   const __half* __restrict__ B,
                                                   float* __restrict__ OutF,
                                                   __half* __restrict__ OutH,
                                                   const float* __restrict__ bias,
                                                   const float* __restrict__ qv,
                                                   int colbase, int lda, int ldb,
                                                   int Ksteps, int Nvalid) {
    constexpr int NTILE = NT * 16;
    constexpr int ASTh = MT * LDKH;
    constexpr int BSTh = NTILE * LDKH;
    constexpr int ACH = MT / 64;
    constexpr int BCH = (NTILE * 4 + 255) / 256;
    constexpr int NB = NTILE * 4;
    constexpr int MTt = MT / 64;
    constexpr int NP = NT / 2;
    extern __shared__ __half dsm[];
    __shared__ float s_bias[224];
    __shared__ float s_qv[224];
    __shared__ float s_red[256];

    int tid = threadIdx.x, lane = tid & 31, wid = tid >> 5;
    int warpM = wid & 3, warpN = wid >> 2;
    int row0 = blockIdx.y * MT;
    int col0 = colbase + blockIdx.x * NTILE;

    for (int i = tid; i < NTILE; i += 256) {
        int c = col0 + i;
        s_bias[i] = (c < Nvalid) ? bias[c] : 0.f;
        if (EPI == 1) s_qv[i] = (c < Nvalid) ? qv[c] : 0.f;
    }
    if (EPI == 1) for (int i = tid; i < MT; i += 256) s_red[i] = 0.f;

    uint32_t su = smem_u32(dsm);
    const __half* aptr[ACH];
    uint32_t aoff[ACH];
#pragma unroll
    for (int j = 0; j < ACH; j++) {
        int i = tid + j * 256;
        int m = i >> 2, kc = i & 3;
        int gr = row0 + m;
        long ro;
        if (EPI == 0) ro = (long)(gr / Tt) * (32 * EeP) + (long)(gr % Tt) * EeP;
        else          ro = (long)gr * lda;
        aptr[j] = A + ro + kc * 8;
        aoff[j] = (uint32_t)(m * 80 + kc * 16);
    }
    const __half* bptr[BCH];
    uint32_t boff[BCH];
    bool bok[BCH];
#pragma unroll
    for (int j = 0; j < BCH; j++) {
        int i = tid + j * 256;
        bok[j] = (i < NB);
        int n = i >> 2, kc = i & 3;
        if (!bok[j]) { n = 0; kc = 0; }
        bptr[j] = B + (long)(col0 + n) * ldb + kc * 8;
        boff[j] = (uint32_t)(n * 80 + kc * 16);
    }

    uint32_t aLd[MTt];
#pragma unroll
    for (int mt = 0; mt < MTt; mt++)
        aLd[mt] = (uint32_t)((warpM * (MT / 4) + mt * 16 + (lane & 15)) * 80 +
                             ((lane >> 4) * 16));
    uint32_t bLd4[(NP > 0) ? NP : 1];
#pragma unroll
    for (int p = 0; p < NP; p++)
        bLd4[p] = (uint32_t)((warpN * NT * 8 + p * 16 + (lane & 7) + ((lane >> 4) * 8)) * 80 +
                             (((lane >> 3) & 1) * 16));
    uint32_t bLd2 = 0;
    if (NT & 1) {
        int l15 = lane & 15;
        bLd2 = (uint32_t)((warpN * NT * 8 + (NT - 1) * 8 + (l15 & 7)) * 80 +
                          ((l15 >> 3) * 16));
    }

    float acc[MTt][NT][4];
#pragma unroll
    for (int i = 0; i < MTt; i++)
#pragma unroll
        for (int j = 0; j < NT; j++)
#pragma unroll
            for (int k = 0; k < 4; k++) acc[i][j][k] = 0.f;

#define LOAD_STAGE(s, buf)                                                        \
    {                                                                             \
        uint32_t ab = su + (uint32_t)(buf) * (ASTh * 2);                          \
        _Pragma("unroll")                                                         \
        for (int j = 0; j < ACH; j++) cpasync16(ab + aoff[j], aptr[j] + (s) * 32);\
        uint32_t bb = su + (uint32_t)(3 * ASTh + (buf) * BSTh) * 2;               \
        _Pragma("unroll")                                                         \
        for (int j = 0; j < BCH; j++)                                             \
            if (bok[j]) cpasync16(bb + boff[j], bptr[j] + (s) * 32);              \
        cpcommit();                                                               \
    }

    LOAD_STAGE(0, 0)
    LOAD_STAGE(1, 1)
    cpwait<1>();
    __syncthreads();

    int r4 = lane >> 2, c4 = lane & 3;

    for (int s = 0; s < Ksteps; s++) {
        int buf = s % 3;
        uint32_t Abase = su + (uint32_t)buf * (ASTh * 2);
        uint32_t Bbase = su + (uint32_t)(3 * ASTh + buf * BSTh) * 2;
#pragma unroll
        for (int kh = 0; kh < 2; kh++) {
            uint32_t khoff = kh * 32;
            uint32_t af[MTt][4], bfr[NT][2];
#pragma unroll
            for (int mt = 0; mt < MTt; mt++)
                ldsm_x4(af[mt][0], af[mt][1], af[mt][2], af[mt][3],
                        Abase + aLd[mt] + khoff);
#pragma unroll
            for (int p = 0; p < NP; p++)
                ldsm_x4(bfr[2 * p][0], bfr[2 * p][1], bfr[2 * p + 1][0], bfr[2 * p + 1][1],
                        Bbase + bLd4[p] + khoff);
            if (NT & 1)
                ldsm_x2(bfr[NT - 1][0], bfr[NT - 1][1], Bbase + bLd2 + khoff);
#pragma unroll
            for (int nt = 0; nt < NT; nt++)
#pragma unroll
                for (int mt = 0; mt < MTt; mt++)
                    mma16816(acc[mt][nt], af[mt], bfr[nt][0], bfr[nt][1]);
        }
        if (s + 2 < Ksteps) {
            int nb = (s + 2) % 3;
            LOAD_STAGE(s + 2, nb)
            cpwait<1>();
        } else {
            cpwait<0>();
        }
        __syncthreads();
    }
#undef LOAD_STAGE

    if (EPI == 0) {
#pragma unroll
        for (int mt = 0; mt < MTt; mt++) {
            int r = row0 + warpM * (MT / 4) + mt * 16 + r4;
#pragma unroll
            for (int nt = 0; nt < NT; nt++) {
                int il = warpN * NT * 8 + nt * 8 + c4 * 2;
                int c = col0 + il;
                if (c < KP) {
                    float b0 = s_bias[il], b1 = s_bias[il + 1];
                    __half2 h0 = __floats2half2_rn(fmaxf(acc[mt][nt][0] + b0, 0.f),
                                                   fmaxf(acc[mt][nt][1] + b1, 0.f));
                    __half2 h1 = __floats2half2_rn(fmaxf(acc[mt][nt][2] + b0, 0.f),
                                                   fmaxf(acc[mt][nt][3] + b1, 0.f));
                    *(__half2*)&OutH[(long)r * KP + c] = h0;
                    *(__half2*)&OutH[(long)(r + 8) * KP + c] = h1;
                }
            }
        }
    } else if (EPI == 1) {
#pragma unroll
        for (int mt = 0; mt < MTt; mt++) {
            float slo = 0.f, shi = 0.f;
#pragma unroll
            for (int nt = 0; nt < NT; nt++) {
                int il = warpN * NT * 8 + nt * 8 + c4 * 2;
                float v0 = s_bias[il], v1 = s_bias[il + 1];
                float q0 = s_qv[il], q1 = s_qv[il + 1];
                slo += htanh(acc[mt][nt][0] + v0) * q0 + htanh(acc[mt][nt][1] + v1) * q1;
                shi += htanh(acc[mt][nt][2] + v0) * q0 + htanh(acc[mt][nt][3] + v1) * q1;
            }
            slo += __shfl_xor_sync(0xffffffffu, slo, 1);
            slo += __shfl_xor_sync(0xffffffffu, slo, 2);
            shi += __shfl_xor_sync(0xffffffffu, shi, 1);
            shi += __shfl_xor_sync(0xffffffffu, shi, 2);
            if (c4 == 0) {
                int rl = warpM * (MT / 4) + mt * 16 + r4;
                atomicAdd(&s_red[rl], slo);
                atomicAdd(&s_red[rl + 8], shi);
            }
        }
        __syncthreads();
        for (int i = tid; i < MT; i += 256) OutF[row0 + i] = s_red[i];
    } else {
#pragma unroll
        for (int mt = 0; mt < MTt; mt++) {
            int r0 = row0 + warpM * (MT / 4) + mt * 16 + r4;
            int r1 = r0 + 8;
#pragma unroll
            for (int nt = 0; nt < NT; nt++) {
                int il = warpN * NT * 8 + nt * 8 + c4 * 2;
                int c = col0 + il;
                float b0 = s_bias[il], b1 = s_bias[il + 1];
                *(float2*)&OutF[(long)r0 * 1200 + c] =
                    make_float2(acc[mt][nt][0] + b0, acc[mt][nt][1] + b1);
                *(float2*)&OutF[(long)r1 * 1200 + c] =
                    make_float2(acc[mt][nt][2] + b0, acc[mt][nt][3] + b1);
            }
        }
    }
}

// ---------------- GX transpose: [r=(b,n)][1200] -> [n][1200][64] ----------------
__global__ __launch_bounds__(256) void gx_transpose() {
    __shared__ float t[64][65];
    int c0 = blockIdx.x * 64;
    int n = blockIdx.y;
    for (int i = threadIdx.x; i < 4096; i += 256) {
        int bb = i >> 6, c = i & 63;
        float v = 0.f;
        if (c0 + c < 1200) v = g_GX[(long)(bb * Nn + n) * 1200 + c0 + c];
        t[c][bb] = v;
    }
    __syncthreads();
    for (int i = threadIdx.x; i < 4096; i += 256) {
        int c = i >> 6, bb = i & 63;
        if (c0 + c < 1200)
            g_GXt[((long)n * 1200 + c0 + c) * 64 + bb] = t[c][bb];
    }
}

// ---------------- softmax over titles ----------------
__global__ void softmax_kernel() {
    int idx = blockIdx.x * blockDim.x + threadIdx.x;
    if (idx >= Bb * Tt) return;
    int b = idx / Tt, t = idx - b * Tt;
    const float* s = g_scores + b * Nn * Tt + t;
    float mx = -1e30f;
    for (int n = 0; n < Nn; n++) mx = fmaxf(mx, s[n * Tt]);
    float sum = 0.f;
    for (int n = 0; n < Nn; n++) sum += __expf(s[n * Tt] - mx);
    float inv = 1.f / sum;
    float* al = g_alpha + b * Nn * Tt + t;
    for (int n = 0; n < Nn; n++) al[n * Tt] = __expf(s[n * Tt] - mx) * inv;
}

// ---------------- weighted sum over words (half2 vectorized) ----------------
__global__ __launch_bounds__(128) void wsum_kernel() {
    int bn = blockIdx.x;
    __shared__ float al[Tt];
    if (threadIdx.x < Tt) al[threadIdx.x] = g_alpha[bn * Tt + threadIdx.x];
    __syncthreads();
    const __half2* Cr = (const __half2*)(g_C + (long)bn * Tt * KP);
    __half2* Er = (__half2*)(g_E + (long)bn * KP);
    for (int f = threadIdx.x; f < KP / 2; f += 128) {
        float ax = 0.f, ay = 0.f;
#pragma unroll
        for (int t = 0; t < Tt; t++) {
            float2 v = __half22float2(Cr[t * (KP / 2) + f]);
            ax += al[t] * v.x;
            ay += al[t] * v.y;
        }
        Er[f] = __floats2half2_rn(ax, ay);
    }
}

// ---------------- tensor-core persistent GRU (25 blocks, fp16 h exchange) ----------------
__global__ __launch_bounds__(256, 1) void gru_tc(const int* __restrict__ uid,
                                                 const float* __restrict__ user_emb,
                                                 const float* __restrict__ b_ih,
                                                 const float* __restrict__ b_hh,
                                                 const int* __restrict__ lens,
                                                 float* __restrict__ out) {
    extern __shared__ __half gsm[];          // [48*408] W | [64*408] h
    __shared__ float s_gate[48][66];
    __half* sW = gsm;
    __half* sH = gsm + 48 * 408;
    int tid = threadIdx.x, lane = tid & 31, wid = tid >> 5;
    int bg = blockIdx.x;
    int warpM = wid & 3, warpN = wid >> 2;

    for (int i = tid; i < 48 * 100; i += 256) {
        int j = i / 100, c4 = (i - j * 100) * 4;
        int grow = (j >> 4) * 400 + bg * 16 + (j & 15);
        *(uint2*)&sW[j * 408 + c4] = *(const uint2*)&g_Whh[(long)grow * Gg + c4];
    }

    int b = tid & 63, gi = tid >> 6;
    int len = lens[b];
    float myh[4], bir[4], biz[4], bin_[4], bhr[4], bhz[4], bhn[4];
    long ub = (long)uid[b] * Gg;
#pragma unroll
    for (int k = 0; k < 4; k++) {
        int gl = gi * 4 + k, gg = bg * 16 + gl;
        myh[k] = user_emb[ub + gg];
        bir[k] = b_ih[gg]; biz[k] = b_ih[400 + gg]; bin_[k] = b_ih[800 + gg];
        bhr[k] = b_hh[gg]; bhz[k] = b_hh[400 + gg]; bhn[k] = b_hh[800 + gg];
    }
    {
        __half2 p01 = __floats2half2_rn(myh[0], myh[1]);
        __half2 p23 = __floats2half2_rn(myh[2], myh[3]);
        uint2 pk = make_uint2(*(uint32_t*)&p01, *(uint32_t*)&p23);
        *(uint2*)&g_hH[0][b * 408 + bg * 16 + gi * 4] = pk;
    }

    uint32_t sHu = smem_u32(sH), sWu = smem_u32(sW);
    uint32_t aLd = sHu + (uint32_t)((warpM * 16 + (lane & 15)) * 816 + ((lane >> 4) * 16));
    uint32_t bLd4 = sWu + (uint32_t)((warpN * 24 + (lane & 7) + ((lane >> 4) * 8)) * 816 +
                                     (((lane >> 3) & 1) * 16));
    int l15 = lane & 15;
    uint32_t bLd2 = sWu + (uint32_t)((warpN * 24 + 16 + (l15 & 7)) * 816 + ((l15 >> 3) * 16));

    for (int n = 0; n < Nn; n++) {
        __threadfence();
        __syncthreads();
        if (tid == 0) {
            atomicAdd(&g_bar[n], 1);
            while (*((volatile int*)&g_bar[n]) < GBLK) { }
        }
        __syncthreads();
        const __half* hbuf = g_hH[n & 1];
        for (int i = tid; i < 64 * 51; i += 256) {
            int row = i / 51, c = i - row * 51;
            cpasync16(sHu + (uint32_t)(row * 816 + c * 16), hbuf + row * 408 + c * 8);
        }
        cpcommit();
        cpwait<0>();
        __syncthreads();

        float acc[3][4] = {};
#pragma unroll 5
        for (int ks = 0; ks < 25; ks++) {
            uint32_t koff = ks * 32;
            uint32_t af[4], b0, b1, b2, b3, c0, c1;
            ldsm_x4(af[0], af[1], af[2], af[3], aLd + koff);
            ldsm_x4(b0, b1, b2, b3, bLd4 + koff);
            ldsm_x2(c0, c1, bLd2 + koff);
            mma16816(acc[0], af, b0, b1);
            mma16816(acc[1], af, b2, b3);
            mma16816(acc[2], af, c0, c1);
        }
        int brow = warpM * 16 + (lane >> 2);
#pragma unroll
        for (int nt = 0; nt < 3; nt++) {
            int col = warpN * 24 + nt * 8 + (lane & 3) * 2;
            s_gate[col][brow] = acc[nt][0];
            s_gate[col + 1][brow] = acc[nt][1];
            s_gate[col][brow + 8] = acc[nt][2];
            s_gate[col + 1][brow + 8] = acc[nt][3];
        }
        __syncthreads();

        const float* gxt = g_GXt + (long)n * 1200 * 64;
#pragma unroll
        for (int k = 0; k < 4; k++) {
            int gl = gi * 4 + k, gg = bg * 16 + gl;
            float hr = s_gate[gl][b] + bhr[k];
            float hz = s_gate[16 + gl][b] + bhz[k];
            float hn = s_gate[32 + gl][b] + bhn[k];
            float xr = gxt[(0 * 400 + gg) * 64 + b] + bir[k];
            float xz = gxt[(400 + gg) * 64 + b] + biz[k];
            float xn = gxt[(800 + gg) * 64 + b] + bin_[k];
            float r = 1.f / (1.f + __expf(-(xr + hr)));
            float z = 1.f / (1.f + __expf(-(xz + hz)));
            float nv = tanhf(xn + r * hn);
            float hnew = (1.f - z) * nv + z * myh[k];
            if (n < len) myh[k] = hnew;
        }
        {
            __half2 p01 = __floats2half2_rn(myh[0], myh[1]);
            __half2 p23 = __floats2half2_rn(myh[2], myh[3]);
            uint2 pk = make_uint2(*(uint32_t*)&p01, *(uint32_t*)&p23);
            *(uint2*)&g_hH[(n + 1) & 1][b * 408 + bg * 16 + gi * 4] = pk;
        }
    }
#pragma unroll
    for (int k = 0; k < 4; k++) {
        int gg = bg * 16 + gi * 4 + k;
        out[b * Gg + gg] = myh[k];
    }
}

// ---------------- launch ----------------
extern "C" void kernel_launch(void* const* d_in, const int* in_sizes, int n_in,
                              void* d_out, int out_size) {
    const int*   user_id  = (const int*)d_in[0];
    const int*   title    = (const int*)d_in[1];
    const int*   hist_len = (const int*)d_in[2];
    const float* word_emb = (const float*)d_in[3];
    const float* conv_w   = (const float*)d_in[4];
    const float* conv_b   = (const float*)d_in[5];
    const float* v        = (const float*)d_in[6];
    const float* vb       = (const float*)d_in[7];
    const float* q        = (const float*)d_in[8];
    const float* user_emb = (const float*)d_in[9];
    const float* W_ih     = (const float*)d_in[10];
    const float* W_hh     = (const float*)d_in[11];
    const float* b_ih     = (const float*)d_in[12];
    const float* b_hh     = (const float*)d_in[13];
    float* out = (float*)d_out;

    __half *Xp, *Wtp, *vTp, *Wihp, *Cp, *Ep;
    float *scp, *GXp;
    int* bar;
    cudaGetSymbolAddress((void**)&Xp, g_X);
    cudaGetSymbolAddress((void**)&Wtp, g_Wt);
    cudaGetSymbolAddress((void**)&vTp, g_vT);
    cudaGetSymbolAddress((void**)&Wihp, g_Wih);
    cudaGetSymbolAddress((void**)&Cp, g_C);
    cudaGetSymbolAddress((void**)&Ep, g_E);
    cudaGetSymbolAddress((void**)&scp, g_scores);
    cudaGetSymbolAddress((void**)&GXp, g_GX);
    cudaGetSymbolAddress((void**)&bar, g_bar);

    auto smemsz = [](int mt, int nt) {
        return (3 * (mt * LDKH + nt * 16 * LDKH)) * (int)sizeof(__half);
    };
    cudaFuncSetAttribute((const void*)hgemm<64, 13, 0, 2>,
                         cudaFuncAttributeMaxDynamicSharedMemorySize, smemsz(64, 13));
    cudaFuncSetAttribute((const void*)hgemm<64, 13, 1, 2>,
                         cudaFuncAttributeMaxDynamicSharedMemorySize, smemsz(64, 13));
    cudaFuncSetAttribute((const void*)hgemm<256, 8, 2, 1>,
                         cudaFuncAttributeMaxDynamicSharedMemorySize, smemsz(256, 8));
    cudaFuncSetAttribute((const void*)hgemm<256, 3, 2, 1>,
                         cudaFuncAttributeMaxDynamicSharedMemorySize, smemsz(256, 3));
    cudaFuncSetAttribute((const void*)gru_tc,
                         cudaFuncAttributeMaxDynamicSharedMemorySize, (48 + 64) * 408 * 2);

    gather_kernel<<<Bb * Nn, 256>>>(title, word_emb);
    wtr_kernel<<<(416 * KCv + 255) / 256, 256>>>(conv_w);
    vtr_kernel<<<(208 * KP + 255) / 256, 256>>>(v);
    wihh_kernel<<<(1200 * KP + 255) / 256, 256>>>(W_ih);
    whh_kernel<<<(1200 * Gg + 255) / 256, 256>>>(W_hh);
    cudaMemsetAsync(bar, 0, 64 * sizeof(int));

    // conv: C = X @ Wt^T + b, ReLU -> half. MT=64, 2 col tiles of 208, 3-stage, 2 CTA/SM
    hgemm<64, 13, 0, 2><<<dim3(2, MROWS / 64), 256, smemsz(64, 13)>>>(
        Xp, Wtp, nullptr, Cp, conv_b, nullptr, 0, 0, KCv, KCv / 32, FNf);
    // attn: scores = sum_c tanh.approx(C @ vT^T + vb) * q, all 208 cols, 2 CTA/SM
    hgemm<64, 13, 1, 2><<<dim3(1, MROWS / 64), 256, smemsz(64, 13)>>>(
        Cp, vTp, scp, nullptr, vb, q, 0, KP, KP, KP / 32, Aa);

    softmax_kernel<<<(Bb * Tt + 255) / 256, 256>>>();
    wsum_kernel<<<Bb * Nn, 128>>>();

    // GX = E @ W_ih^T + b_ih, row-major [r][1200], then transpose to [n][1200][64]
    hgemm<256, 8, 2, 1><<<dim3(9, 13), 256, smemsz(256, 8)>>>(
        Ep, Wihp, GXp, nullptr, b_ih, nullptr, 0, KP, KP, KP / 32, 1200);
    hgemm<256, 3, 2, 1><<<dim3(1, 13), 256, smemsz(256, 3)>>>(
        Ep, Wihp, GXp, nullptr, b_ih, nullptr, 1152, KP, KP, KP / 32, 1200);
    gx_transpose<<<dim3(19, Nn), 256>>>();

    gru_tc<<<GBLK, 256, (48 + 64) * 408 * 2>>>(user_id, user_emb, b_ih, b_hh, hist_len, out);
}

// round 16
// speedup vs baseline: 1.0309x; 1.0309x over previous
#include <cuda_runtime.h>
#include <cuda_fp16.h>
#include <cstdint>

#define Bb 64
#define Nn 50
#define Tt 30
#define Ee 300
#define EeP 320
#define FNf 400
#define Aa 200
#define Gg 400
#define KCv 960            // conv GEMM K = 3*320
#define KP 416             // padded K for attn/GX
#define MROWS (Bb*Nn*Tt)   // 96000
#define LDKH 40            // smem k-stride in halves (32 + 8 pad)
#define GBLK 25            // GRU blocks

// ---------------- scratch ----------------
__device__ __half g_X[(long)Bb * Nn * 32 * EeP];   // gathered embeddings
__device__ __half g_Wt[416 * KCv];                 // conv weights [416][960], rows>=400 zero
__device__ __half g_vT[208 * KP];                  // v^T padded [208][416]
__device__ __half g_Wih[1280 * KP];                // W_ih padded [1280][416], rows>=1200 zero
__device__ __half g_Whh[1200 * Gg];                // W_hh fp16 [1200][400]
__device__ __half g_C[(long)MROWS * KP];           // conv out; pad cols 0
__device__ float  g_scores[MROWS];
__device__ __half g_E[3328 * KP];                  // news embed (rows>=3200 stay 0)
__device__ float  g_GX[3328L * 1200];              // GX row-major [r][1200]
__device__ float  g_GXt[Nn * 1200 * Bb];           // transposed: [n][3G][b]
__device__ __align__(16) __half g_hH[2][Bb * 408]; // fp16 h exchange, ping-pong
__device__ int    g_bar[64];

// ---------------- helpers ----------------
__device__ __forceinline__ uint32_t smem_u32(const void* p) {
    uint32_t a;
    asm("{ .reg .u64 t; cvta.to.shared.u64 t, %1; cvt.u32.u64 %0, t; }" : "=r"(a) : "l"(p));
    return a;
}
__device__ __forceinline__ float htanh(float x) {
    float r; asm("tanh.approx.f32 %0, %1;" : "=f"(r) : "f"(x)); return r;
}
__device__ __forceinline__ void cpasync16(uint32_t dst, const void* src) {
    asm volatile("cp.async.cg.shared.global [%0], [%1], 16;" :: "r"(dst), "l"(src));
}
__device__ __forceinline__ void cpcommit() { asm volatile("cp.async.commit_group;" ::: "memory"); }
template <int N> __device__ __forceinline__ void cpwait() {
    asm volatile("cp.async.wait_group %0;" :: "n"(N) : "memory");
}
__device__ __forceinline__ void mma16816(float* c, const uint32_t* a, uint32_t b0, uint32_t b1) {
    asm volatile("mma.sync.aligned.m16n8k16.row.col.f32.f16.f16.f32 "
                 "{%0,%1,%2,%3}, {%4,%5,%6,%7}, {%8,%9}, {%0,%1,%2,%3};"
                 : "+f"(c[0]), "+f"(c[1]), "+f"(c[2]), "+f"(c[3])
                 : "r"(a[0]), "r"(a[1]), "r"(a[2]), "r"(a[3]), "r"(b0), "r"(b1));
}
__device__ __forceinline__ void ldsm_x4(uint32_t& r0, uint32_t& r1, uint32_t& r2, uint32_t& r3,
                                        uint32_t addr) {
    asm volatile("ldmatrix.sync.aligned.m8n8.x4.shared.b16 {%0,%1,%2,%3}, [%4];"
                 : "=r"(r0), "=r"(r1), "=r"(r2), "=r"(r3) : "r"(addr));
}
__device__ __forceinline__ void ldsm_x2(uint32_t& r0, uint32_t& r1, uint32_t addr) {
    asm volatile("ldmatrix.sync.aligned.m8n8.x2.shared.b16 {%0,%1}, [%2];"
                 : "=r"(r0), "=r"(r1) : "r"(addr));
}

// ---------------- unified prep kernel ----------------
// blocks [0, 3200): gather; [3200, 4760): wtr; [4760, 5098): vtr;
// [5098, 7178): wihh (1280 rows); [7178, 9053): whh
#define PREP_G0 3200
#define PREP_G1 (PREP_G0 + 1560)
#define PREP_G2 (PREP_G1 + 338)
#define PREP_G3 (PREP_G2 + 2080)
#define PREP_G4 (PREP_G3 + 1875)
__global__ __launch_bounds__(256) void prep_kernel(const int* __restrict__ title,
                                                   const float* __restrict__ word_emb,
                                                   const float* __restrict__ conv_w,
                                                   const float* __restrict__ v,
                                                   const float* __restrict__ W_ih,
                                                   const float* __restrict__ W_hh) {
    int blk = blockIdx.x;
    if (blk < PREP_G0) {
        int bn = blk;
        __half* X = g_X + (long)bn * 32 * EeP;
        const __half z = __float2half(0.f);
        for (int i = threadIdx.x; i < EeP; i += 256) { X[i] = z; X[31 * EeP + i] = z; }
        const int* tw = title + bn * Tt;
        for (int idx = threadIdx.x; idx < Tt * EeP; idx += 256) {
            int s = idx / EeP, e = idx - s * EeP;
            float x = (e < Ee) ? word_emb[(long)tw[s] * Ee + e] : 0.f;
            X[(s + 1) * EeP + e] = __float2half_rn(x);
        }
    } else if (blk < PREP_G1) {
        int i = (blk - PREP_G0) * 256 + threadIdx.x;
        if (i < 416 * KCv) {
            int n = i / KCv, k = i - n * KCv;
            int tap = k / EeP, e = k - tap * EeP;
            float x = (n < FNf && e < Ee) ? conv_w[(tap * Ee + e) * FNf + n] : 0.f;
            g_Wt[i] = __float2half_rn(x);
        }
    } else if (blk < PREP_G2) {
        int i = (blk - PREP_G1) * 256 + threadIdx.x;
        if (i < 208 * KP) {
            int a = i / KP, f = i - a * KP;
            float x = (a < Aa && f < FNf) ? v[f * Aa + a] : 0.f;
            g_vT[i] = __float2half_rn(x);
        }
    } else if (blk < PREP_G3) {
        int i = (blk - PREP_G2) * 256 + threadIdx.x;
        if (i < 1280 * KP) {
            int n = i / KP, k = i - n * KP;
            float x = (n < 1200 && k < FNf) ? W_ih[n * FNf + k] : 0.f;
            g_Wih[i] = __float2half_rn(x);
        }
    } else {
        int i = (blk - PREP_G3) * 256 + threadIdx.x;
        if (i < 1200 * Gg) g_Whh[i] = __float2half_rn(W_hh[i]);
    }
}

// ---------------- fp16 cp.async GEMM (3-stage) with ldmatrix fragments ----------------
// EPI 0: conv rows via g_X map; bias+ReLU -> half OutH[.][416]
// EPI 1: attn; tanh.approx(+vb)*q block-reduce -> OutF[row] (g_scores)
// EPI 2: GX; bias; plain fp32 store to OutF[r][1200], guarded c < Nvalid
template <int MT, int NT, int EPI, int MINB>
__global__ __launch_bounds__(256, MINB) void hgemm(const __half* __restrict__ A,
                                                   const __half* __restrict__ B,
                                                   float* __restrict__ OutF,
                                                   __half* __restrict__ OutH,
                                                   const float* __restrict__ bias,
                                                   const float* __restrict__ qv,
                                                   int colbase, int lda, int ldb,
                                                   int Ksteps, int Nvalid) {
    constexpr int NTILE = NT * 16;
    constexpr int ASTh = MT * LDKH;
    constexpr int BSTh = NTILE * LDKH;
    constexpr int ACH = MT / 64;
    constexpr int BCH = (NTILE * 4 + 255) / 256;
    constexpr int NB = NTILE * 4;
    constexpr int MTt = MT / 64;
    constexpr int NP = NT / 2;
    extern __shared__ __half dsm[];
    __shared__ float s_bias[224];
    __shared__ float s_qv[224];
    __shared__ float s_red[256];

    int tid = threadIdx.x, lane = tid & 31, wid = tid >> 5;
    int warpM = wid & 3, warpN = wid >> 2;
    int row0 = blockIdx.y * MT;
    int col0 = colbase + blockIdx.x * NTILE;

    for (int i = tid; i < NTILE; i += 256) {
        int c = col0 + i;
        s_bias[i] = (c < Nvalid) ? bias[c] : 0.f;
        if (EPI == 1) s_qv[i] = (c < Nvalid) ? qv[c] : 0.f;
    }
    if (EPI == 1) for (int i = tid; i < MT; i += 256) s_red[i] = 0.f;

    uint32_t su = smem_u32(dsm);
    const __half* aptr[ACH];
    uint32_t aoff[ACH];
#pragma unroll
    for (int j = 0; j < ACH; j++) {
        int i = tid + j * 256;
        int m = i >> 2, kc = i & 3;
        int gr = row0 + m;
        long ro;
        if (EPI == 0) ro = (long)(gr / Tt) * (32 * EeP) + (long)(gr % Tt) * EeP;
        else          ro = (long)gr * lda;
        aptr[j] = A + ro + kc * 8;
        aoff[j] = (uint32_t)(m * 80 + kc * 16);
    }
    const __half* bptr[BCH];
    uint32_t boff[BCH];
    bool bok[BCH];
#pragma unroll
    for (int j = 0; j < BCH; j++) {
        int i = tid + j * 256;
        bok[j] = (i < NB);
        int n = i >> 2, kc = i & 3;
        if (!bok[j]) { n = 0; kc = 0; }
        bptr[j] = B + (long)(col0 + n) * ldb + kc * 8;
        boff[j] = (uint32_t)(n * 80 + kc * 16);
    }

    uint32_t aLd[MTt];
#pragma unroll
    for (int mt = 0; mt < MTt; mt++)
        aLd[mt] = (uint32_t)((warpM * (MT / 4) + mt * 16 + (lane & 15)) * 80 +
                             ((lane >> 4) * 16));
    uint32_t bLd4[(NP > 0) ? NP : 1];
#pragma unroll
    for (int p = 0; p < NP; p++)
        bLd4[p] = (uint32_t)((warpN * NT * 8 + p * 16 + (lane & 7) + ((lane >> 4) * 8)) * 80 +
                             (((lane >> 3) & 1) * 16));
    uint32_t bLd2 = 0;
    if (NT & 1) {
        int l15 = lane & 15;
        bLd2 = (uint32_t)((warpN * NT * 8 + (NT - 1) * 8 + (l15 & 7)) * 80 +
                          ((l15 >> 3) * 16));
    }

    float acc[MTt][NT][4];
#pragma unroll
    for (int i = 0; i < MTt; i++)
#pragma unroll
        for (int j = 0; j < NT; j++)
#pragma unroll
            for (int k = 0; k < 4; k++) acc[i][j][k] = 0.f;

#define LOAD_STAGE(s, buf)                                                        \
    {                                                                             \
        uint32_t ab = su + (uint32_t)(buf) * (ASTh * 2);                          \
        _Pragma("unroll")                                                         \
        for (int j = 0; j < ACH; j++) cpasync16(ab + aoff[j], aptr[j] + (s) * 32);\
        uint32_t bb = su + (uint32_t)(3 * ASTh + (buf) * BSTh) * 2;               \
        _Pragma("unroll")                                                         \
        for (int j = 0; j < BCH; j++)                                             \
            if (bok[j]) cpasync16(bb + boff[j], bptr[j] + (s) * 32);              \
        cpcommit();                                                               \
    }

    LOAD_STAGE(0, 0)
    LOAD_STAGE(1, 1)
    cpwait<1>();
    __syncthreads();

    int r4 = lane >> 2, c4 = lane & 3;

    for (int s = 0; s < Ksteps; s++) {
        int buf = s % 3;
        uint32_t Abase = su + (uint32_t)buf * (ASTh * 2);
        uint32_t Bbase = su + (uint32_t)(3 * ASTh + buf * BSTh) * 2;
#pragma unroll
        for (int kh = 0; kh < 2; kh++) {
            uint32_t khoff = kh * 32;
            uint32_t af[MTt][4], bfr[NT][2];
#pragma unroll
            for (int mt = 0; mt < MTt; mt++)
                ldsm_x4(af[mt][0], af[mt][1], af[mt][2], af[mt][3],
                        Abase + aLd[mt] + khoff);
#pragma unroll
            for (int p = 0; p < NP; p++)
                ldsm_x4(bfr[2 * p][0], bfr[2 * p][1], bfr[2 * p + 1][0], bfr[2 * p + 1][1],
                        Bbase + bLd4[p] + khoff);
            if (NT & 1)
                ldsm_x2(bfr[NT - 1][0], bfr[NT - 1][1], Bbase + bLd2 + khoff);
#pragma unroll
            for (int nt = 0; nt < NT; nt++)
#pragma unroll
                for (int mt = 0; mt < MTt; mt++)
                    mma16816(acc[mt][nt], af[mt], bfr[nt][0], bfr[nt][1]);
        }
        if (s + 2 < Ksteps) {
            int nb = (s + 2) % 3;
            LOAD_STAGE(s + 2, nb)
            cpwait<1>();
        } else {
            cpwait<0>();
        }
        __syncthreads();
    }
#undef LOAD_STAGE

    if (EPI == 0) {
#pragma unroll
        for (int mt = 0; mt < MTt; mt++) {
            int r = row0 + warpM * (MT / 4) + mt * 16 + r4;
#pragma unroll
            for (int nt = 0; nt < NT; nt++) {
                int il = warpN * NT * 8 + nt * 8 + c4 * 2;
                int c = col0 + il;
                if (c < KP) {
                    float b0 = s_bias[il], b1 = s_bias[il + 1];
                    __half2 h0 = __floats2half2_rn(fmaxf(acc[mt][nt][0] + b0, 0.f),
                                                   fmaxf(acc[mt][nt][1] + b1, 0.f));
                    __half2 h1 = __floats2half2_rn(fmaxf(acc[mt][nt][2] + b0, 0.f),
                                                   fmaxf(acc[mt][nt][3] + b1, 0.f));
                    *(__half2*)&OutH[(long)r * KP + c] = h0;
                    *(__half2*)&OutH[(long)(r + 8) * KP + c] = h1;
                }
            }
        }
    } else if (EPI == 1) {
#pragma unroll
        for (int mt = 0; mt < MTt; mt++) {
            float slo = 0.f, shi = 0.f;
#pragma unroll
            for (int nt = 0; nt < NT; nt++) {
                int il = warpN * NT * 8 + nt * 8 + c4 * 2;
                float v0 = s_bias[il], v1 = s_bias[il + 1];
                float q0 = s_qv[il], q1 = s_qv[il + 1];
                slo += htanh(acc[mt][nt][0] + v0) * q0 + htanh(acc[mt][nt][1] + v1) * q1;
                shi += htanh(acc[mt][nt][2] + v0) * q0 + htanh(acc[mt][nt][3] + v1) * q1;
            }
            slo += __shfl_xor_sync(0xffffffffu, slo, 1);
            slo += __shfl_xor_sync(0xffffffffu, slo, 2);
            shi += __shfl_xor_sync(0xffffffffu, shi, 1);
            shi += __shfl_xor_sync(0xffffffffu, shi, 2);
            if (c4 == 0) {
                int rl = warpM * (MT / 4) + mt * 16 + r4;
                atomicAdd(&s_red[rl], slo);
                atomicAdd(&s_red[rl + 8], shi);
            }
        }
        __syncthreads();
        for (int i = tid; i < MT; i += 256) OutF[row0 + i] = s_red[i];
    } else {
#pragma unroll
        for (int mt = 0; mt < MTt; mt++) {
            int r0 = row0 + warpM * (MT / 4) + mt * 16 + r4;
            int r1 = r0 + 8;
#pragma unroll
            for (int nt = 0; nt < NT; nt++) {
                int il = warpN * NT * 8 + nt * 8 + c4 * 2;
                int c = col0 + il;
                if (c < Nvalid) {
                    float b0 = s_bias[il], b1 = s_bias[il + 1];
                    *(float2*)&OutF[(long)r0 * 1200 + c] =
                        make_float2(acc[mt][nt][0] + b0, acc[mt][nt][1] + b1);
                    *(float2*)&OutF[(long)r1 * 1200 + c] =
                        make_float2(acc[mt][nt][2] + b0, acc[mt][nt][3] + b1);
                }
            }
        }
    }
}

// ---------------- GX transpose: [r=(b,n)][1200] -> [n][1200][64] ----------------
__global__ __launch_bounds__(256) void gx_transpose() {
    __shared__ float t[64][65];
    int c0 = blockIdx.x * 64;
    int n = blockIdx.y;
    for (int i = threadIdx.x; i < 4096; i += 256) {
        int bb = i >> 6, c = i & 63;
        float v = 0.f;
        if (c0 + c < 1200) v = g_GX[(long)(bb * Nn + n) * 1200 + c0 + c];
        t[c][bb] = v;
    }
    __syncthreads();
    for (int i = threadIdx.x; i < 4096; i += 256) {
        int c = i >> 6, bb = i & 63;
        if (c0 + c < 1200)
            g_GXt[((long)n * 1200 + c0 + c) * 64 + bb] = t[c][bb];
    }
}

// ---------------- fused softmax + weighted sum ----------------
// block bn=(b,n): compute alpha[b,n,t] (softmax over titles n') in-block, then E row.
__global__ __launch_bounds__(128) void wsum_kernel() {
    __shared__ float s_sc[Nn * Tt];     // scores for this batch: [n'][t]
    __shared__ float al[Tt];
    int bn = blockIdx.x;
    int b = bn / Nn, n = bn - b * Nn;
    const float* sb = g_scores + b * Nn * Tt;
    for (int i = threadIdx.x; i < Nn * Tt; i += 128) s_sc[i] = sb[i];
    __syncthreads();
    if (threadIdx.x < Tt) {
        int t = threadIdx.x;
        float mx = -1e30f;
        for (int np = 0; np < Nn; np++) mx = fmaxf(mx, s_sc[np * Tt + t]);
        float sum = 0.f;
        for (int np = 0; np < Nn; np++) sum += __expf(s_sc[np * Tt + t] - mx);
        al[t] = __expf(s_sc[n * Tt + t] - mx) / sum;
    }
    __syncthreads();
    const __half2* Cr = (const __half2*)(g_C + (long)bn * Tt * KP);
    __half2* Er = (__half2*)(g_E + (long)bn * KP);
    for (int f = threadIdx.x; f < KP / 2; f += 128) {
        float ax = 0.f, ay = 0.f;
#pragma unroll
        for (int t = 0; t < Tt; t++) {
            float2 v = __half22float2(Cr[t * (KP / 2) + f]);
            ax += al[t] * v.x;
            ay += al[t] * v.y;
        }
        Er[f] = __floats2half2_rn(ax, ay);
    }
}

// ---------------- tensor-core persistent GRU (25 blocks, fp16 h exchange) ----------------
__global__ __launch_bounds__(256, 1) void gru_tc(const int* __restrict__ uid,
                                                 const float* __restrict__ user_emb,
                                                 const float* __restrict__ b_ih,
                                                 const float* __restrict__ b_hh,
                                                 const int* __restrict__ lens,
                                                 float* __restrict__ out) {
    extern __shared__ __half gsm[];          // [48*408] W | [64*408] h
    __shared__ float s_gate[48][66];
    __half* sW = gsm;
    __half* sH = gsm + 48 * 408;
    int tid = threadIdx.x, lane = tid & 31, wid = tid >> 5;
    int bg = blockIdx.x;
    int warpM = wid & 3, warpN = wid >> 2;

    for (int i = tid; i < 48 * 100; i += 256) {
        int j = i / 100, c4 = (i - j * 100) * 4;
        int grow = (j >> 4) * 400 + bg * 16 + (j & 15);
        *(uint2*)&sW[j * 408 + c4] = *(const uint2*)&g_Whh[(long)grow * Gg + c4];
    }

    int b = tid & 63, gi = tid >> 6;
    int len = lens[b];
    float myh[4], bir[4], biz[4], bin_[4], bhr[4], bhz[4], bhn[4];
    long ub = (long)uid[b] * Gg;
#pragma unroll
    for (int k = 0; k < 4; k++) {
        int gl = gi * 4 + k, gg = bg * 16 + gl;
        myh[k] = user_emb[ub + gg];
        bir[k] = b_ih[gg]; biz[k] = b_ih[400 + gg]; bin_[k] = b_ih[800 + gg];
        bhr[k] = b_hh[gg]; bhz[k] = b_hh[400 + gg]; bhn[k] = b_hh[800 + gg];
    }
    {
        __half2 p01 = __floats2half2_rn(myh[0], myh[1]);
        __half2 p23 = __floats2half2_rn(myh[2], myh[3]);
        uint2 pk = make_uint2(*(uint32_t*)&p01, *(uint32_t*)&p23);
        *(uint2*)&g_hH[0][b * 408 + bg * 16 + gi * 4] = pk;
    }

    uint32_t sHu = smem_u32(sH), sWu = smem_u32(sW);
    uint32_t aLd = sHu + (uint32_t)((warpM * 16 + (lane & 15)) * 816 + ((lane >> 4) * 16));
    uint32_t bLd4 = sWu + (uint32_t)((warpN * 24 + (lane & 7) + ((lane >> 4) * 8)) * 816 +
                                     (((lane >> 3) & 1) * 16));
    int l15 = lane & 15;
    uint32_t bLd2 = sWu + (uint32_t)((warpN * 24 + 16 + (l15 & 7)) * 816 + ((l15 >> 3) * 16));

    for (int n = 0; n < Nn; n++) {
        __threadfence();
        __syncthreads();
        if (tid == 0) {
            atomicAdd(&g_bar[n], 1);
            while (*((volatile int*)&g_bar[n]) < GBLK) { }
        }
        __syncthreads();
        const __half* hbuf = g_hH[n & 1];
        for (int i = tid; i < 64 * 51; i += 256) {
            int row = i / 51, c = i - row * 51;
            cpasync16(sHu + (uint32_t)(row * 816 + c * 16), hbuf + row * 408 + c * 8);
        }
        cpcommit();
        cpwait<0>();
        __syncthreads();

        float acc[3][4] = {};
#pragma unroll 5
        for (int ks = 0; ks < 25; ks++) {
            uint32_t koff = ks * 32;
            uint32_t af[4], b0, b1, b2, b3, c0, c1;
            ldsm_x4(af[0], af[1], af[2], af[3], aLd + koff);
            ldsm_x4(b0, b1, b2, b3, bLd4 + koff);
            ldsm_x2(c0, c1, bLd2 + koff);
            mma16816(acc[0], af, b0, b1);
            mma16816(acc[1], af, b2, b3);
            mma16816(acc[2], af, c0, c1);
        }
        int brow = warpM * 16 + (lane >> 2);
#pragma unroll
        for (int nt = 0; nt < 3; nt++) {
            int col = warpN * 24 + nt * 8 + (lane & 3) * 2;
            s_gate[col][brow] = acc[nt][0];
            s_gate[col + 1][brow] = acc[nt][1];
            s_gate[col][brow + 8] = acc[nt][2];
            s_gate[col + 1][brow + 8] = acc[nt][3];
        }
        __syncthreads();

        const float* gxt = g_GXt + (long)n * 1200 * 64;
#pragma unroll
        for (int k = 0; k < 4; k++) {
            int gl = gi * 4 + k, gg = bg * 16 + gl;
            float hr = s_gate[gl][b] + bhr[k];
            float hz = s_gate[16 + gl][b] + bhz[k];
            float hn = s_gate[32 + gl][b] + bhn[k];
            float xr = gxt[(0 * 400 + gg) * 64 + b] + bir[k];
            float xz = gxt[(400 + gg) * 64 + b] + biz[k];
            float xn = gxt[(800 + gg) * 64 + b] + bin_[k];
            float r = 1.f / (1.f + __expf(-(xr + hr)));
            float z = 1.f / (1.f + __expf(-(xz + hz)));
            float nv = tanhf(xn + r * hn);
            float hnew = (1.f - z) * nv + z * myh[k];
            if (n < len) myh[k] = hnew;
        }
        {
            __half2 p01 = __floats2half2_rn(myh[0], myh[1]);
            __half2 p23 = __floats2half2_rn(myh[2], myh[3]);
            uint2 pk = make_uint2(*(uint32_t*)&p01, *(uint32_t*)&p23);
            *(uint2*)&g_hH[(n + 1) & 1][b * 408 + bg * 16 + gi * 4] = pk;
        }
    }
#pragma unroll
    for (int k = 0; k < 4; k++) {
        int gg = bg * 16 + gi * 4 + k;
        out[b * Gg + gg] = myh[k];
    }
}

// ---------------- launch ----------------
extern "C" void kernel_launch(void* const* d_in, const int* in_sizes, int n_in,
                              void* d_out, int out_size) {
    const int*   user_id  = (const int*)d_in[0];
    const int*   title    = (const int*)d_in[1];
    const int*   hist_len = (const int*)d_in[2];
    const float* word_emb = (const float*)d_in[3];
    const float* conv_w   = (const float*)d_in[4];
    const float* conv_b   = (const float*)d_in[5];
    const float* v        = (const float*)d_in[6];
    const float* vb       = (const float*)d_in[7];
    const float* q        = (const float*)d_in[8];
    const float* user_emb = (const float*)d_in[9];
    const float* W_ih     = (const float*)d_in[10];
    const float* W_hh     = (const float*)d_in[11];
    const float* b_ih     = (const float*)d_in[12];
    const float* b_hh     = (const float*)d_in[13];
    float* out = (float*)d_out;

    __half *Xp, *Wtp, *vTp, *Wihp, *Cp, *Ep;
    float *scp, *GXp;
    int* bar;
    cudaGetSymbolAddress((void**)&Xp, g_X);
    cudaGetSymbolAddress((void**)&Wtp, g_Wt);
    cudaGetSymbolAddress((void**)&vTp, g_vT);
    cudaGetSymbolAddress((void**)&Wihp, g_Wih);
    cudaGetSymbolAddress((void**)&Cp, g_C);
    cudaGetSymbolAddress((void**)&Ep, g_E);
    cudaGetSymbolAddress((void**)&scp, g_scores);
    cudaGetSymbolAddress((void**)&GXp, g_GX);
    cudaGetSymbolAddress((void**)&bar, g_bar);

    auto smemsz = [](int mt, int nt) {
        return (3 * (mt * LDKH + nt * 16 * LDKH)) * (int)sizeof(__half);
    };
    cudaFuncSetAttribute((const void*)hgemm<64, 13, 0, 2>,
                         cudaFuncAttributeMaxDynamicSharedMemorySize, smemsz(64, 13));
    cudaFuncSetAttribute((const void*)hgemm<64, 13, 1, 2>,
                         cudaFuncAttributeMaxDynamicSharedMemorySize, smemsz(64, 13));
    cudaFuncSetAttribute((const void*)hgemm<256, 8, 2, 1>,
                         cudaFuncAttributeMaxDynamicSharedMemorySize, smemsz(256, 8));
    cudaFuncSetAttribute((const void*)gru_tc,
                         cudaFuncAttributeMaxDynamicSharedMemorySize, (48 + 64) * 408 * 2);

    prep_kernel<<<PREP_G4, 256>>>(title, word_emb, conv_w, v, W_ih, W_hh);
    cudaMemsetAsync(bar, 0, 64 * sizeof(int));

    // conv: C = X @ Wt^T + b, ReLU -> half. MT=64, 2 col tiles of 208, 3-stage, 2 CTA/SM
    hgemm<64, 13, 0, 2><<<dim3(2, MROWS / 64), 256, smemsz(64, 13)>>>(
        Xp, Wtp, nullptr, Cp, conv_b, nullptr, 0, 0, KCv, KCv / 32, FNf);
    // attn: scores = sum_c tanh.approx(C @ vT^T + vb) * q, all 208 cols, 2 CTA/SM
    hgemm<64, 13, 1, 2><<<dim3(1, MROWS / 64), 256, smemsz(64, 13)>>>(
        Cp, vTp, scp, nullptr, vb, q, 0, KP, KP, KP / 32, Aa);

    // fused softmax + weighted sum -> g_E
    wsum_kernel<<<Bb * Nn, 128>>>();

    // GX = E @ W_ih^T + b_ih : single launch, 10 col tiles of 128 (guarded at 1200)
    hgemm<256, 8, 2, 1><<<dim3(10, 13), 256, smemsz(256, 8)>>>(
        Ep, Wihp, GXp, nullptr, b_ih, nullptr, 0, KP, KP, KP / 32, 1200);
    gx_transpose<<<dim3(19, Nn), 256>>>();

    gru_tc<<<GBLK, 256, (48 + 64) * 408 * 2>>>(user_id, user_emb, b_ih, b_hh, hist_len, out);
}

// round 17
// speedup vs baseline: 1.1221x; 1.0885x over previous
#include <cuda_runtime.h>
#include <cuda_fp16.h>
#include <cstdint>

#define Bb 64
#define Nn 50
#define Tt 30
#define Ee 300
#define EeP 320
#define FNf 400
#define Aa 200
#define Gg 400
#define KCv 960            // conv GEMM K = 3*320
#define KP 416             // padded K for attn/GX
#define MROWS (Bb*Nn*Tt)   // 96000
#define LDKH 40            // smem k-stride in halves (32 + 8 pad)
#define GBLK 25            // GRU blocks

// ---------------- scratch ----------------
__device__ __half g_X[(long)Bb * Nn * 32 * EeP];   // gathered embeddings
__device__ __half g_Wt[416 * KCv];                 // conv weights [416][960], rows>=400 zero
__device__ __half g_vT[208 * KP];                  // v^T padded [208][416]
__device__ __half g_Wih[1280 * KP];                // W_ih padded [1280][416], rows>=1200 zero
__device__ __half g_Whh[1200 * Gg];                // W_hh fp16 [1200][400]
__device__ __half g_C[(long)MROWS * KP];           // conv out; pad cols 0
__device__ float  g_scores[MROWS];
__device__ __half g_E[3328 * KP];                  // news embed (rows>=3200 stay 0)
__device__ float  g_GX[3328L * 1200];              // GX row-major [r][1200]
__device__ float  g_GXt[Nn * 1200 * Bb];           // transposed: [n][3G][b]
__device__ __align__(16) __half g_hH[2][Bb * 408]; // fp16 h exchange, ping-pong
__device__ int    g_bar[64];

// ---------------- helpers ----------------
__device__ __forceinline__ uint32_t smem_u32(const void* p) {
    uint32_t a;
    asm("{ .reg .u64 t; cvta.to.shared.u64 t, %1; cvt.u32.u64 %0, t; }" : "=r"(a) : "l"(p));
    return a;
}
__device__ __forceinline__ float htanh(float x) {
    float r; asm("tanh.approx.f32 %0, %1;" : "=f"(r) : "f"(x)); return r;
}
__device__ __forceinline__ void cpasync16(uint32_t dst, const void* src) {
    asm volatile("cp.async.cg.shared.global [%0], [%1], 16;" :: "r"(dst), "l"(src));
}
__device__ __forceinline__ void cpcommit() { asm volatile("cp.async.commit_group;" ::: "memory"); }
template <int N> __device__ __forceinline__ void cpwait() {
    asm volatile("cp.async.wait_group %0;" :: "n"(N) : "memory");
}
__device__ __forceinline__ void mma16816(float* c, const uint32_t* a, uint32_t b0, uint32_t b1) {
    asm volatile("mma.sync.aligned.m16n8k16.row.col.f32.f16.f16.f32 "
                 "{%0,%1,%2,%3}, {%4,%5,%6,%7}, {%8,%9}, {%0,%1,%2,%3};"
                 : "+f"(c[0]), "+f"(c[1]), "+f"(c[2]), "+f"(c[3])
                 : "r"(a[0]), "r"(a[1]), "r"(a[2]), "r"(a[3]), "r"(b0), "r"(b1));
}
__device__ __forceinline__ void ldsm_x4(uint32_t& r0, uint32_t& r1, uint32_t& r2, uint32_t& r3,
                                        uint32_t addr) {
    asm volatile("ldmatrix.sync.aligned.m8n8.x4.shared.b16 {%0,%1,%2,%3}, [%4];"
                 : "=r"(r0), "=r"(r1), "=r"(r2), "=r"(r3) : "r"(addr));
}
__device__ __forceinline__ void ldsm_x2(uint32_t& r0, uint32_t& r1, uint32_t addr) {
    asm volatile("ldmatrix.sync.aligned.m8n8.x2.shared.b16 {%0,%1}, [%2];"
                 : "=r"(r0), "=r"(r1) : "r"(addr));
}

// ---------------- unified prep kernel (also resets g_bar) ----------------
#define PREP_G0 3200
#define PREP_G1 (PREP_G0 + 1560)
#define PREP_G2 (PREP_G1 + 338)
#define PREP_G3 (PREP_G2 + 2080)
#define PREP_G4 (PREP_G3 + 1875)
#define PREP_TOT (PREP_G4 + 1)
__global__ __launch_bounds__(256) void prep_kernel(const int* __restrict__ title,
                                                   const float* __restrict__ word_emb,
                                                   const float* __restrict__ conv_w,
                                                   const float* __restrict__ v,
                                                   const float* __restrict__ W_ih,
                                                   const float* __restrict__ W_hh) {
    int blk = blockIdx.x;
    if (blk < PREP_G0) {
        int bn = blk;
        __half* X = g_X + (long)bn * 32 * EeP;
        const __half z = __float2half(0.f);
        for (int i = threadIdx.x; i < EeP; i += 256) { X[i] = z; X[31 * EeP + i] = z; }
        const int* tw = title + bn * Tt;
        for (int idx = threadIdx.x; idx < Tt * EeP; idx += 256) {
            int s = idx / EeP, e = idx - s * EeP;
            float x = (e < Ee) ? word_emb[(long)tw[s] * Ee + e] : 0.f;
            X[(s + 1) * EeP + e] = __float2half_rn(x);
        }
    } else if (blk < PREP_G1) {
        int i = (blk - PREP_G0) * 256 + threadIdx.x;
        if (i < 416 * KCv) {
            int n = i / KCv, k = i - n * KCv;
            int tap = k / EeP, e = k - tap * EeP;
            float x = (n < FNf && e < Ee) ? conv_w[(tap * Ee + e) * FNf + n] : 0.f;
            g_Wt[i] = __float2half_rn(x);
        }
    } else if (blk < PREP_G2) {
        int i = (blk - PREP_G1) * 256 + threadIdx.x;
        if (i < 208 * KP) {
            int a = i / KP, f = i - a * KP;
            float x = (a < Aa && f < FNf) ? v[f * Aa + a] : 0.f;
            g_vT[i] = __float2half_rn(x);
        }
    } else if (blk < PREP_G3) {
        int i = (blk - PREP_G2) * 256 + threadIdx.x;
        if (i < 1280 * KP) {
            int n = i / KP, k = i - n * KP;
            float x = (n < 1200 && k < FNf) ? W_ih[n * FNf + k] : 0.f;
            g_Wih[i] = __float2half_rn(x);
        }
    } else if (blk < PREP_G4) {
        int i = (blk - PREP_G3) * 256 + threadIdx.x;
        if (i < 1200 * Gg) g_Whh[i] = __float2half_rn(W_hh[i]);
    } else {
        if (threadIdx.x < 64) g_bar[threadIdx.x] = 0;
    }
}

// ---------------- fp16 cp.async GEMM (3-stage) with ldmatrix fragments ----------------
template <int MT, int NT, int EPI, int MINB>
__global__ __launch_bounds__(256, MINB) void hgemm(const __half* __restrict__ A,
                                                   const __half* __restrict__ B,
                                                   float* __restrict__ OutF,
                                                   __half* __restrict__ OutH,
                                                   const float* __restrict__ bias,
                                                   const float* __restrict__ qv,
                                                   int colbase, int lda, int ldb,
                                                   int Ksteps, int Nvalid) {
    constexpr int NTILE = NT * 16;
    constexpr int ASTh = MT * LDKH;
    constexpr int BSTh = NTILE * LDKH;
    constexpr int ACH = MT / 64;
    constexpr int BCH = (NTILE * 4 + 255) / 256;
    constexpr int NB = NTILE * 4;
    constexpr int MTt = MT / 64;
    constexpr int NP = NT / 2;
    extern __shared__ __half dsm[];
    __shared__ float s_bias[224];
    __shared__ float s_qv[224];
    __shared__ float s_red[256];

    int tid = threadIdx.x, lane = tid & 31, wid = tid >> 5;
    int warpM = wid & 3, warpN = wid >> 2;
    int row0 = blockIdx.y * MT;
    int col0 = colbase + blockIdx.x * NTILE;

    for (int i = tid; i < NTILE; i += 256) {
        int c = col0 + i;
        s_bias[i] = (c < Nvalid) ? bias[c] : 0.f;
        if (EPI == 1) s_qv[i] = (c < Nvalid) ? qv[c] : 0.f;
    }
    if (EPI == 1) for (int i = tid; i < MT; i += 256) s_red[i] = 0.f;

    uint32_t su = smem_u32(dsm);
    const __half* aptr[ACH];
    uint32_t aoff[ACH];
#pragma unroll
    for (int j = 0; j < ACH; j++) {
        int i = tid + j * 256;
        int m = i >> 2, kc = i & 3;
        int gr = row0 + m;
        long ro;
        if (EPI == 0) ro = (long)(gr / Tt) * (32 * EeP) + (long)(gr % Tt) * EeP;
        else          ro = (long)gr * lda;
        aptr[j] = A + ro + kc * 8;
        aoff[j] = (uint32_t)(m * 80 + kc * 16);
    }
    const __half* bptr[BCH];
    uint32_t boff[BCH];
    bool bok[BCH];
#pragma unroll
    for (int j = 0; j < BCH; j++) {
        int i = tid + j * 256;
        bok[j] = (i < NB);
        int n = i >> 2, kc = i & 3;
        if (!bok[j]) { n = 0; kc = 0; }
        bptr[j] = B + (long)(col0 + n) * ldb + kc * 8;
        boff[j] = (uint32_t)(n * 80 + kc * 16);
    }

    uint32_t aLd[MTt];
#pragma unroll
    for (int mt = 0; mt < MTt; mt++)
        aLd[mt] = (uint32_t)((warpM * (MT / 4) + mt * 16 + (lane & 15)) * 80 +
                             ((lane >> 4) * 16));
    uint32_t bLd4[(NP > 0) ? NP : 1];
#pragma unroll
    for (int p = 0; p < NP; p++)
        bLd4[p] = (uint32_t)((warpN * NT * 8 + p * 16 + (lane & 7) + ((lane >> 4) * 8)) * 80 +
                             (((lane >> 3) & 1) * 16));
    uint32_t bLd2 = 0;
    if (NT & 1) {
        int l15 = lane & 15;
        bLd2 = (uint32_t)((warpN * NT * 8 + (NT - 1) * 8 + (l15 & 7)) * 80 +
                          ((l15 >> 3) * 16));
    }

    float acc[MTt][NT][4];
#pragma unroll
    for (int i = 0; i < MTt; i++)
#pragma unroll
        for (int j = 0; j < NT; j++)
#pragma unroll
            for (int k = 0; k < 4; k++) acc[i][j][k] = 0.f;

#define LOAD_STAGE(s, buf)                                                        \
    {                                                                             \
        uint32_t ab = su + (uint32_t)(buf) * (ASTh * 2);                          \
        _Pragma("unroll")                                                         \
        for (int j = 0; j < ACH; j++) cpasync16(ab + aoff[j], aptr[j] + (s) * 32);\
        uint32_t bb = su + (uint32_t)(3 * ASTh + (buf) * BSTh) * 2;               \
        _Pragma("unroll")                                                         \
        for (int j = 0; j < BCH; j++)                                             \
            if (bok[j]) cpasync16(bb + boff[j], bptr[j] + (s) * 32);              \
        cpcommit();                                                               \
    }

    LOAD_STAGE(0, 0)
    LOAD_STAGE(1, 1)
    cpwait<1>();
    __syncthreads();

    int r4 = lane >> 2, c4 = lane & 3;

    for (int s = 0; s < Ksteps; s++) {
        int buf = s % 3;
        uint32_t Abase = su + (uint32_t)buf * (ASTh * 2);
        uint32_t Bbase = su + (uint32_t)(3 * ASTh + buf * BSTh) * 2;
#pragma unroll
        for (int kh = 0; kh < 2; kh++) {
            uint32_t khoff = kh * 32;
            uint32_t af[MTt][4], bfr[NT][2];
#pragma unroll
            for (int mt = 0; mt < MTt; mt++)
                ldsm_x4(af[mt][0], af[mt][1], af[mt][2], af[mt][3],
                        Abase + aLd[mt] + khoff);
#pragma unroll
            for (int p = 0; p < NP; p++)
                ldsm_x4(bfr[2 * p][0], bfr[2 * p][1], bfr[2 * p + 1][0], bfr[2 * p + 1][1],
                        Bbase + bLd4[p] + khoff);
            if (NT & 1)
                ldsm_x2(bfr[NT - 1][0], bfr[NT - 1][1], Bbase + bLd2 + khoff);
#pragma unroll
            for (int nt = 0; nt < NT; nt++)
#pragma unroll
                for (int mt = 0; mt < MTt; mt++)
                    mma16816(acc[mt][nt], af[mt], bfr[nt][0], bfr[nt][1]);
        }
        if (s + 2 < Ksteps) {
            int nb = (s + 2) % 3;
            LOAD_STAGE(s + 2, nb)
            cpwait<1>();
        } else {
            cpwait<0>();
        }
        __syncthreads();
    }
#undef LOAD_STAGE

    if (EPI == 0) {
#pragma unroll
        for (int mt = 0; mt < MTt; mt++) {
            int r = row0 + warpM * (MT / 4) + mt * 16 + r4;
#pragma unroll
            for (int nt = 0; nt < NT; nt++) {
                int il = warpN * NT * 8 + nt * 8 + c4 * 2;
                int c = col0 + il;
                if (c < KP) {
                    float b0 = s_bias[il], b1 = s_bias[il + 1];
                    __half2 h0 = __floats2half2_rn(fmaxf(acc[mt][nt][0] + b0, 0.f),
                                                   fmaxf(acc[mt][nt][1] + b1, 0.f));
                    __half2 h1 = __floats2half2_rn(fmaxf(acc[mt][nt][2] + b0, 0.f),
                                                   fmaxf(acc[mt][nt][3] + b1, 0.f));
                    *(__half2*)&OutH[(long)r * KP + c] = h0;
                    *(__half2*)&OutH[(long)(r + 8) * KP + c] = h1;
                }
            }
        }
    } else if (EPI == 1) {
#pragma unroll
        for (int mt = 0; mt < MTt; mt++) {
            float slo = 0.f, shi = 0.f;
#pragma unroll
            for (int nt = 0; nt < NT; nt++) {
                int il = warpN * NT * 8 + nt * 8 + c4 * 2;
                float v0 = s_bias[il], v1 = s_bias[il + 1];
                float q0 = s_qv[il], q1 = s_qv[il + 1];
                slo += htanh(acc[mt][nt][0] + v0) * q0 + htanh(acc[mt][nt][1] + v1) * q1;
                shi += htanh(acc[mt][nt][2] + v0) * q0 + htanh(acc[mt][nt][3] + v1) * q1;
            }
            slo += __shfl_xor_sync(0xffffffffu, slo, 1);
            slo += __shfl_xor_sync(0xffffffffu, slo, 2);
            shi += __shfl_xor_sync(0xffffffffu, shi, 1);
            shi += __shfl_xor_sync(0xffffffffu, shi, 2);
            if (c4 == 0) {
                int rl = warpM * (MT / 4) + mt * 16 + r4;
                atomicAdd(&s_red[rl], slo);
                atomicAdd(&s_red[rl + 8], shi);
            }
        }
        __syncthreads();
        for (int i = tid; i < MT; i += 256) OutF[row0 + i] = s_red[i];
    } else {
#pragma unroll
        for (int mt = 0; mt < MTt; mt++) {
            int r0 = row0 + warpM * (MT / 4) + mt * 16 + r4;
            int r1 = r0 + 8;
#pragma unroll
            for (int nt = 0; nt < NT; nt++) {
                int il = warpN * NT * 8 + nt * 8 + c4 * 2;
                int c = col0 + il;
                if (c < Nvalid) {
                    float b0 = s_bias[il], b1 = s_bias[il + 1];
                    *(float2*)&OutF[(long)r0 * 1200 + c] =
                        make_float2(acc[mt][nt][0] + b0, acc[mt][nt][1] + b1);
                    *(float2*)&OutF[(long)r1 * 1200 + c] =
                        make_float2(acc[mt][nt][2] + b0, acc[mt][nt][3] + b1);
                }
            }
        }
    }
}

// ---------------- GX transpose: [r=(b,n)][1200] -> [n][1200][64] ----------------
__global__ __launch_bounds__(256) void gx_transpose() {
    __shared__ float t[64][65];
    int c0 = blockIdx.x * 64;
    int n = blockIdx.y;
    for (int i = threadIdx.x; i < 4096; i += 256) {
        int bb = i >> 6, c = i & 63;
        float v = 0.f;
        if (c0 + c < 1200) v = g_GX[(long)(bb * Nn + n) * 1200 + c0 + c];
        t[c][bb] = v;
    }
    __syncthreads();
    for (int i = threadIdx.x; i < 4096; i += 256) {
        int c = i >> 6, bb = i & 63;
        if (c0 + c < 1200)
            g_GXt[((long)n * 1200 + c0 + c) * 64 + bb] = t[c][bb];
    }
}

// ---------------- fused softmax + weighted sum ----------------
__global__ __launch_bounds__(128) void wsum_kernel() {
    __shared__ float s_sc[Nn * Tt];
    __shared__ float al[Tt];
    int bn = blockIdx.x;
    int b = bn / Nn, n = bn - b * Nn;
    const float* sb = g_scores + b * Nn * Tt;
    for (int i = threadIdx.x; i < Nn * Tt; i += 128) s_sc[i] = sb[i];
    __syncthreads();
    if (threadIdx.x < Tt) {
        int t = threadIdx.x;
        float mx = -1e30f;
        for (int np = 0; np < Nn; np++) mx = fmaxf(mx, s_sc[np * Tt + t]);
        float sum = 0.f;
        for (int np = 0; np < Nn; np++) sum += __expf(s_sc[np * Tt + t] - mx);
        al[t] = __expf(s_sc[n * Tt + t] - mx) / sum;
    }
    __syncthreads();
    const __half2* Cr = (const __half2*)(g_C + (long)bn * Tt * KP);
    __half2* Er = (__half2*)(g_E + (long)bn * KP);
    for (int f = threadIdx.x; f < KP / 2; f += 128) {
        float ax = 0.f, ay = 0.f;
#pragma unroll
        for (int t = 0; t < Tt; t++) {
            float2 v = __half22float2(Cr[t * (KP / 2) + f]);
            ax += al[t] * v.x;
            ay += al[t] * v.y;
        }
        Er[f] = __floats2half2_rn(ax, ay);
    }
}

// ---------------- tensor-core persistent GRU (fp16 h exchange, gxt smem prefetch) ----------------
__global__ __launch_bounds__(256, 1) void gru_tc(const int* __restrict__ uid,
                                                 const float* __restrict__ user_emb,
                                                 const float* __restrict__ b_ih,
                                                 const float* __restrict__ b_hh,
                                                 const int* __restrict__ lens,
                                                 float* __restrict__ out) {
    extern __shared__ __half gsm[];          // [48*408] W | [64*408] h
    __shared__ float s_gate[48][66];
    __shared__ float s_gxt[2][48 * 64];      // prefetched x-gates, double-buffered
    __half* sW = gsm;
    __half* sH = gsm + 48 * 408;
    int tid = threadIdx.x, lane = tid & 31, wid = tid >> 5;
    int bg = blockIdx.x;
    int warpM = wid & 3, warpN = wid >> 2;

    for (int i = tid; i < 48 * 100; i += 256) {
        int j = i / 100, c4 = (i - j * 100) * 4;
        int grow = (j >> 4) * 400 + bg * 16 + (j & 15);
        *(uint2*)&sW[j * 408 + c4] = *(const uint2*)&g_Whh[(long)grow * Gg + c4];
    }

    int b = tid & 63, gi = tid >> 6;
    int len = lens[b];
    float myh[4], bir[4], biz[4], bin_[4], bhr[4], bhz[4], bhn[4];
    long ub = (long)uid[b] * Gg;
#pragma unroll
    for (int k = 0; k < 4; k++) {
        int gl = gi * 4 + k, gg = bg * 16 + gl;
        myh[k] = user_emb[ub + gg];
        bir[k] = b_ih[gg]; biz[k] = b_ih[400 + gg]; bin_[k] = b_ih[800 + gg];
        bhr[k] = b_hh[gg]; bhz[k] = b_hh[400 + gg]; bhn[k] = b_hh[800 + gg];
    }
    {
        __half2 p01 = __floats2half2_rn(myh[0], myh[1]);
        __half2 p23 = __floats2half2_rn(myh[2], myh[3]);
        uint2 pk = make_uint2(*(uint32_t*)&p01, *(uint32_t*)&p23);
        *(uint2*)&g_hH[0][b * 408 + bg * 16 + gi * 4] = pk;
    }

    uint32_t sHu = smem_u32(sH), sWu = smem_u32(sW);
    uint32_t gxtu = smem_u32(s_gxt);
    uint32_t aLd = sHu + (uint32_t)((warpM * 16 + (lane & 15)) * 816 + ((lane >> 4) * 16));
    uint32_t bLd4 = sWu + (uint32_t)((warpN * 24 + (lane & 7) + ((lane >> 4) * 8)) * 816 +
                                     (((lane >> 3) & 1) * 16));
    int l15 = lane & 15;
    uint32_t bLd2 = sWu + (uint32_t)((warpN * 24 + 16 + (l15 & 7)) * 816 + ((l15 >> 3) * 16));

    // gxt prefetch: 48 rows x 64 floats = 768 16B chunks, 3 per thread
#define GXT_PREFETCH(n)                                                           \
    {                                                                             \
        const float* src = g_GXt + (long)(n) * 1200 * 64;                         \
        _Pragma("unroll")                                                         \
        for (int jj = 0; jj < 3; jj++) {                                          \
            int i = tid + jj * 256;                                               \
            int j = i >> 4, cc = (i & 15) * 4;                                    \
            int grow = (j >> 4) * 400 + bg * 16 + (j & 15);                       \
            cpasync16(gxtu + (uint32_t)((((n) & 1) * 3072 + j * 64 + cc) * 4),    \
                      src + (long)grow * 64 + cc);                                \
        }                                                                         \
        cpcommit();                                                               \
    }

    GXT_PREFETCH(0)

    for (int n = 0; n < Nn; n++) {
        __threadfence();
        __syncthreads();
        if (tid == 0) {
            atomicAdd(&g_bar[n], 1);
            while (*((volatile int*)&g_bar[n]) < GBLK) { }
        }
        __syncthreads();
        const __half* hbuf = g_hH[n & 1];
        for (int i = tid; i < 64 * 51; i += 256) {
            int row = i / 51, c = i - row * 51;
            cpasync16(sHu + (uint32_t)(row * 816 + c * 16), hbuf + row * 408 + c * 8);
        }
        cpcommit();
        cpwait<0>();     // waits h AND the in-flight gxt[n]
        __syncthreads();

        float acc[3][4] = {};
#pragma unroll 5
        for (int ks = 0; ks < 25; ks++) {
            uint32_t koff = ks * 32;
            uint32_t af[4], b0, b1, b2, b3, c0, c1;
            ldsm_x4(af[0], af[1], af[2], af[3], aLd + koff);
            ldsm_x4(b0, b1, b2, b3, bLd4 + koff);
            ldsm_x2(c0, c1, bLd2 + koff);
            mma16816(acc[0], af, b0, b1);
            mma16816(acc[1], af, b2, b3);
            mma16816(acc[2], af, c0, c1);
        }
        int brow = warpM * 16 + (lane >> 2);
#pragma unroll
        for (int nt = 0; nt < 3; nt++) {
            int col = warpN * 24 + nt * 8 + (lane & 3) * 2;
            s_gate[col][brow] = acc[nt][0];
            s_gate[col + 1][brow] = acc[nt][1];
            s_gate[col][brow + 8] = acc[nt][2];
            s_gate[col + 1][brow + 8] = acc[nt][3];
        }
        __syncthreads();

        const float* gx = s_gxt[n & 1];
#pragma unroll
        for (int k = 0; k < 4; k++) {
            int gl = gi * 4 + k;
            float hr = s_gate[gl][b] + bhr[k];
            float hz = s_gate[16 + gl][b] + bhz[k];
            float hn = s_gate[32 + gl][b] + bhn[k];
            float xr = gx[(0 * 16 + gl) * 64 + b] + bir[k];
            float xz = gx[(16 + gl) * 64 + b] + biz[k];
            float xn = gx[(32 + gl) * 64 + b] + bin_[k];
            float r = 1.f / (1.f + __expf(-(xr + hr)));
            float z = 1.f / (1.f + __expf(-(xz + hz)));
            float nv = tanhf(xn + r * hn);
            float hnew = (1.f - z) * nv + z * myh[k];
            if (n < len) myh[k] = hnew;
        }
        {
            __half2 p01 = __floats2half2_rn(myh[0], myh[1]);
            __half2 p23 = __floats2half2_rn(myh[2], myh[3]);
            uint2 pk = make_uint2(*(uint32_t*)&p01, *(uint32_t*)&p23);
            *(uint2*)&g_hH[(n + 1) & 1][b * 408 + bg * 16 + gi * 4] = pk;
        }
        if (n + 1 < Nn) GXT_PREFETCH(n + 1)
    }
#undef GXT_PREFETCH
#pragma unroll
    for (int k = 0; k < 4; k++) {
        int gg = bg * 16 + gi * 4 + k;
        out[b * Gg + gg] = myh[k];
    }
}

// ---------------- launch ----------------
extern "C" void kernel_launch(void* const* d_in, const int* in_sizes, int n_in,
                              void* d_out, int out_size) {
    const int*   user_id  = (const int*)d_in[0];
    const int*   title    = (const int*)d_in[1];
    const int*   hist_len = (const int*)d_in[2];
    const float* word_emb = (const float*)d_in[3];
    const float* conv_w   = (const float*)d_in[4];
    const float* conv_b   = (const float*)d_in[5];
    const float* v        = (const float*)d_in[6];
    const float* vb       = (const float*)d_in[7];
    const float* q        = (const float*)d_in[8];
    const float* user_emb = (const float*)d_in[9];
    const float* W_ih     = (const float*)d_in[10];
    const float* W_hh     = (const float*)d_in[11];
    const float* b_ih     = (const float*)d_in[12];
    const float* b_hh     = (const float*)d_in[13];
    float* out = (float*)d_out;

    __half *Xp, *Wtp, *vTp, *Wihp, *Cp, *Ep;
    float *scp, *GXp;
    cudaGetSymbolAddress((void**)&Xp, g_X);
    cudaGetSymbolAddress((void**)&Wtp, g_Wt);
    cudaGetSymbolAddress((void**)&vTp, g_vT);
    cudaGetSymbolAddress((void**)&Wihp, g_Wih);
    cudaGetSymbolAddress((void**)&Cp, g_C);
    cudaGetSymbolAddress((void**)&Ep, g_E);
    cudaGetSymbolAddress((void**)&scp, g_scores);
    cudaGetSymbolAddress((void**)&GXp, g_GX);

    auto smemsz = [](int mt, int nt) {
        return (3 * (mt * LDKH + nt * 16 * LDKH)) * (int)sizeof(__half);
    };
    cudaFuncSetAttribute((const void*)hgemm<64, 13, 0, 2>,
                         cudaFuncAttributeMaxDynamicSharedMemorySize, smemsz(64, 13));
    cudaFuncSetAttribute((const void*)hgemm<64, 13, 1, 2>,
                         cudaFuncAttributeMaxDynamicSharedMemorySize, smemsz(64, 13));
    cudaFuncSetAttribute((const void*)hgemm<256, 8, 2, 1>,
                         cudaFuncAttributeMaxDynamicSharedMemorySize, smemsz(256, 8));
    cudaFuncSetAttribute((const void*)gru_tc,
                         cudaFuncAttributeMaxDynamicSharedMemorySize, (48 + 64) * 408 * 2);

    prep_kernel<<<PREP_TOT, 256>>>(title, word_emb, conv_w, v, W_ih, W_hh);

    // conv: C = X @ Wt^T + b, ReLU -> half. MT=64, 2 col tiles of 208, 3-stage, 2 CTA/SM
    hgemm<64, 13, 0, 2><<<dim3(2, MROWS / 64), 256, smemsz(64, 13)>>>(
        Xp, Wtp, nullptr, Cp, conv_b, nullptr, 0, 0, KCv, KCv / 32, FNf);
    // attn: scores = sum_c tanh.approx(C @ vT^T + vb) * q, all 208 cols, 2 CTA/SM
    hgemm<64, 13, 1, 2><<<dim3(1, MROWS / 64), 256, smemsz(64, 13)>>>(
        Cp, vTp, scp, nullptr, vb, q, 0, KP, KP, KP / 32, Aa);

    // fused softmax + weighted sum -> g_E
    wsum_kernel<<<Bb * Nn, 128>>>();

    // GX = E @ W_ih^T + b_ih : single launch, 10 col tiles of 128 (guarded at 1200)
    hgemm<256, 8, 2, 1><<<dim3(10, 13), 256, smemsz(256, 8)>>>(
        Ep, Wihp, GXp, nullptr, b_ih, nullptr, 0, KP, KP, KP / 32, 1200);
    gx_transpose<<<dim3(19, Nn), 256>>>();

    gru_tc<<<GBLK, 256, (48 + 64) * 408 * 2>>>(user_id, user_emb, b_ih, b_hh, hist_len, out);
}